// round 16
// baseline (speedup 1.0000x reference)
#include <cuda_runtime.h>
#include <cstdint>
#include <math.h>

// Problem shape (fixed): B=4, H=8, S=1024, D=64
#define SLEN 1024
#define HD   64
#define NBH  32
#define NROWS (NBH * SLEN)           // 32768
#define NTOT  ((size_t)NROWS * SLEN) // 33554432 = 2^25
#define NBINS 4096                   // bits >> 18 : 8 exp + 5 mantissa bits
#define KSPLIT 8

typedef unsigned long long ull;

// ---------------- scratch ---------------------------------------------------
__device__ float g_score[NROWS * SLEN];          // 128 MiB raw scores
__device__ unsigned int g_hist[NBINS];           // 16 KiB counts
__device__ float g_ttab[NBINS + 1];              // edge t values
__device__ float g_invq[NROWS];
__device__ float g_invk[NROWS];
__device__ float g_pout[KSPLIT * NROWS * HD];    // 64 MiB partial outputs
__device__ float g_psum[KSPLIT * NROWS];         // partial row |sums|

// ---------------- f32x2 helpers (sm_103a) -----------------------------------
__device__ __forceinline__ ull pack2(float a, float b) {
    ull r; asm("mov.b64 %0, {%1,%2};" : "=l"(r) : "f"(a), "f"(b)); return r;
}
__device__ __forceinline__ ull fma2(ull a, ull b, ull c) {
    ull d; asm("fma.rn.f32x2 %0, %1, %2, %3;" : "=l"(d) : "l"(a), "l"(b), "l"(c));
    return d;
}
__device__ __forceinline__ float2 unpack2(ull v) {
    float2 f; asm("mov.b64 {%0,%1}, %2;" : "=f"(f.x), "=f"(f.y) : "l"(v));
    return f;
}
__device__ __forceinline__ unsigned sw(unsigned a) {      // 128B-line swizzle
    return a ^ ((a >> 3) & 0x70u);
}

// ---------------- kernel 1: inverse row norms (+ hist zeroing) --------------
__global__ __launch_bounds__(256) void norms_kernel(const float* __restrict__ Q,
                                                    const float* __restrict__ K) {
    if (blockIdx.x < 16) g_hist[blockIdx.x * 256 + threadIdx.x] = 0u;
    int w = (blockIdx.x * 256 + threadIdx.x) >> 5;
    int lane = threadIdx.x & 31;
    const float* src; float* dst; int row;
    if (w < NROWS) { src = Q; dst = g_invq; row = w; }
    else           { src = K; dst = g_invk; row = w - NROWS; }
    const float* p = src + (size_t)row * HD;
    float a = p[lane], b = p[lane + 32];
    float s = a * a + b * b;
    #pragma unroll
    for (int o = 16; o; o >>= 1) s += __shfl_xor_sync(0xffffffffu, s, o);
    if (lane == 0) dst[row] = 1.0f / (sqrtf(s) + 1e-5f);
}

// ---------------- kernel 2: score GEMM + smem-private histogram -------------
__global__ __launch_bounds__(256, 2) void score_kernel(const float* __restrict__ Q,
                                                       const float* __restrict__ K) {
    __shared__ __align__(16) float Qsk[32 * 132];  // [k][row] (hist0 alias)
    __shared__ __align__(16) float Ks[32 * 128];   // k-major SW128 (hist1 alias)
    int bh = blockIdx.z;
    int i0 = blockIdx.y * 128, j0 = blockIdx.x * 128;
    const float* Qb = Q + (size_t)bh * SLEN * HD;
    const float* Kb = K + (size_t)bh * SLEN * HD;
    int tid = threadIdx.x;
    int tx = tid & 15, ty = tid >> 4;

    ull acc[8][4];
    #pragma unroll
    for (int ii = 0; ii < 8; ii++)
        #pragma unroll
        for (int p = 0; p < 4; p++) acc[ii][p] = 0ull;

    #pragma unroll
    for (int c = 0; c < 2; c++) {          // k chunks of 32 (ascending order!)
        int k0 = c * 32;
        if (c) __syncthreads();
        #pragma unroll
        for (int pass = 0; pass < 4; pass++) {
            int row = (tid >> 3) + pass * 32;
            int kq = (tid & 7) * 4;
            float4 q4 = *(const float4*)&Qb[(i0 + row) * HD + k0 + kq];
            Qsk[(kq + 0) * 132 + row] = q4.x;
            Qsk[(kq + 1) * 132 + row] = q4.y;
            Qsk[(kq + 2) * 132 + row] = q4.z;
            Qsk[(kq + 3) * 132 + row] = q4.w;
            float4 k4 = *(const float4*)&Kb[(j0 + row) * HD + k0 + kq];
            #pragma unroll
            for (int e = 0; e < 4; e++) {
                unsigned a = (unsigned)(kq + e) * 512u + (unsigned)row * 4u;
                Ks[sw(a) >> 2] = (&k4.x)[e];
            }
        }
        __syncthreads();
        #pragma unroll
        for (int k = 0; k < 32; k++) {
            unsigned a0 = (unsigned)k * 512u + (unsigned)tx * 32u;
            float4 b0 = *(const float4*)&Ks[sw(a0) >> 2];
            float4 b1 = *(const float4*)&Ks[sw(a0 + 16u) >> 2];
            ull bv0 = pack2(b0.x, b0.y), bv1 = pack2(b0.z, b0.w);
            ull bv2 = pack2(b1.x, b1.y), bv3 = pack2(b1.z, b1.w);
            float4 av0 = *(const float4*)&Qsk[k * 132 + ty * 8];
            float4 av1 = *(const float4*)&Qsk[k * 132 + ty * 8 + 4];
            const float* avp0 = &av0.x;
            const float* avp1 = &av1.x;
            #pragma unroll
            for (int ii = 0; ii < 4; ii++) {
                ull a2 = pack2(avp0[ii], avp0[ii]);
                acc[ii][0] = fma2(a2, bv0, acc[ii][0]);
                acc[ii][1] = fma2(a2, bv1, acc[ii][1]);
                acc[ii][2] = fma2(a2, bv2, acc[ii][2]);
                acc[ii][3] = fma2(a2, bv3, acc[ii][3]);
            }
            #pragma unroll
            for (int ii = 0; ii < 4; ii++) {
                ull a2 = pack2(avp1[ii], avp1[ii]);
                acc[4 + ii][0] = fma2(a2, bv0, acc[4 + ii][0]);
                acc[4 + ii][1] = fma2(a2, bv1, acc[4 + ii][1]);
                acc[4 + ii][2] = fma2(a2, bv2, acc[4 + ii][2]);
                acc[4 + ii][3] = fma2(a2, bv3, acc[4 + ii][3]);
            }
        }
    }

    // ---- epilogue: tiles dead; alias as two u16-packed lane-parity subhists --
    unsigned* hist0 = (unsigned*)Qsk;     // 2048 u32 = 4096 u16 counters
    unsigned* hist1 = (unsigned*)Ks;      // 2048 u32
    __syncthreads();
    for (int i = tid; i < 2048; i += 256) { hist0[i] = 0u; hist1[i] = 0u; }
    __syncthreads();
    unsigned* hsel = (tid & 1) ? hist1 : hist0;

    int jb = j0 + tx * 8;
    float ikv[8];
    #pragma unroll
    for (int jj = 0; jj < 8; jj++) ikv[jj] = g_invk[bh * SLEN + jb + jj];
    #pragma unroll
    for (int ii = 0; ii < 8; ii++) {
        int row = bh * SLEN + i0 + ty * 8 + ii;
        float iq = g_invq[row];
        float2 c0 = unpack2(acc[ii][0]);
        float2 c1 = unpack2(acc[ii][1]);
        float2 c2 = unpack2(acc[ii][2]);
        float2 c3 = unpack2(acc[ii][3]);
        float v[8];
        v[0] = c0.x * iq * ikv[0]; v[1] = c0.y * iq * ikv[1];
        v[2] = c1.x * iq * ikv[2]; v[3] = c1.y * iq * ikv[3];
        v[4] = c2.x * iq * ikv[4]; v[5] = c2.y * iq * ikv[5];
        v[6] = c3.x * iq * ikv[6]; v[7] = c3.y * iq * ikv[7];
        size_t idx = (size_t)row * SLEN + jb;
        *(float4*)&g_score[idx]     = make_float4(v[0], v[1], v[2], v[3]);
        *(float4*)&g_score[idx + 4] = make_float4(v[4], v[5], v[6], v[7]);
        #pragma unroll
        for (int e = 0; e < 8; e++) {
            unsigned bin = __float_as_uint(fabsf(v[e])) >> 18;   // < 4096
            atomicAdd(&hsel[bin >> 1], 1u << ((bin & 1u) * 16u));
        }
    }

    __syncthreads();
    for (int i = tid; i < 2048; i += 256) {
        unsigned p0 = hist0[i], p1 = hist1[i];
        unsigned lo = (p0 & 0xFFFFu) + (p1 & 0xFFFFu);
        unsigned hi = (p0 >> 16) + (p1 >> 16);
        if (lo) atomicAdd(&g_hist[2 * i],     lo);
        if (hi) atomicAdd(&g_hist[2 * i + 1], hi);
    }
}

// ---------------- kernel 2.5: scan 4096 bins + edge t table (1 block) -------
__global__ __launch_bounds__(1024) void scan_ttab_kernel() {
    __shared__ unsigned ws[32];
    int tid = threadIdx.x;
    int lane = tid & 31, wid = tid >> 5;
    unsigned c0 = g_hist[tid * 4], c1 = g_hist[tid * 4 + 1];
    unsigned c2 = g_hist[tid * 4 + 2], c3 = g_hist[tid * 4 + 3];
    unsigned tsum = c0 + c1 + c2 + c3;
    unsigned incl = tsum;
    #pragma unroll
    for (int o = 1; o < 32; o <<= 1) {
        unsigned n = __shfl_up_sync(0xffffffffu, incl, o);
        if (lane >= o) incl += n;
    }
    if (lane == 31) ws[wid] = incl;
    __syncthreads();
    if (wid == 0) {
        unsigned v = ws[lane];
        #pragma unroll
        for (int o = 1; o < 32; o <<= 1) {
            unsigned n = __shfl_up_sync(0xffffffffu, v, o);
            if (lane >= o) v += n;
        }
        ws[lane] = v;
    }
    __syncthreads();
    unsigned excl = incl - tsum + (wid ? ws[wid - 1] : 0u);
    const float sA = 1.0f / 33554431.0f;   // 1/(n-1)
    const float sB = 1.0f / 33554432.0f;   // 1/n
    unsigned e0 = excl, e1 = e0 + c0, e2 = e1 + c1, e3 = e2 + c2;
    g_ttab[tid * 4]     = -__logf(fmaf((float)e0, sA, sB));
    g_ttab[tid * 4 + 1] = -__logf(fmaf((float)e1, sA, sB));
    g_ttab[tid * 4 + 2] = -__logf(fmaf((float)e2, sA, sB));
    g_ttab[tid * 4 + 3] = -__logf(fmaf((float)e3, sA, sB));
    if (tid == 1023)
        g_ttab[4096] = -__logf(fmaf((float)(e3 + c3), sA, sB));
}

// ---------------- kernel 3: fused transform + partial out GEMM ---------------
// 1024 blocks = 128 row-groups (256 rows) x 8 k-splits (128 k-cols, 4 chunks).
// Math: 8 rows x 8 cols per thread -> 128 MAC/smem-beat (vs 85 before).
// Row |sums|: k-sliced post-pass per chunk (k = j*8+tx), conflict-free, then
// one shfl reduce across the 8 tx threads at the end. 2 blocks/SM.
__global__ __launch_bounds__(256, 2) void out_kernel(const float* __restrict__ V) {
    extern __shared__ __align__(16) float dsm[];
    float* Ts     = dsm;                  // [256][33]  (33.8 KB)
    float* Vs     = Ts + 256 * 33;        // [32][64] SW128 (8 KB)
    float* ttab_s = Vs + 32 * 64;         // 4097 floats (16.4 KB)

    int blk = blockIdx.x;                // 0..1023
    int ks = blk & 7;                    // k-split index
    int rg = blk >> 3;                   // row group 0..127
    int bh = rg >> 2;
    int i0 = rg * 256;
    int kbase = ks * 128;                // first k col of this split
    const float* Vb = V + (size_t)bh * SLEN * HD;
    int tid = threadIdx.x;
    int tx = tid & 7, ty = tid >> 3;     // math: 8 col-groups x 32 row-groups (8 rows each)
    int lane = tid & 31, wrp = tid >> 5;
    int kv = tid >> 3, d8 = (tid & 7) * 8;   // V staging map

    for (int i = tid; i < NBINS + 1; i += 256) ttab_s[i] = g_ttab[i];
    __syncthreads();

    ull acc[8][4];
    #pragma unroll
    for (int ii = 0; ii < 8; ii++)
        #pragma unroll
        for (int p = 0; p < 4; p++) acc[ii][p] = 0ull;
    float srow8[8];
    #pragma unroll
    for (int ii = 0; ii < 8; ii++) srow8[ii] = 0.0f;

    const float* pbase = g_score + (size_t)i0 * SLEN + kbase + lane;
    const float* vrow_ptr = &Vb[(kbase + kv) * HD + d8];

    // prefetch V chunk 0
    float4 vv0 = *(const float4*)vrow_ptr;
    float4 vv1 = *(const float4*)(vrow_ptr + 4);

    for (int c = 0; c < 4; c++) {
        if (c) __syncthreads();          // previous math done before overwrite
        // consume prefetched V -> Vs (swizzled)
        {
            unsigned a = (unsigned)kv * 256u + (unsigned)d8 * 4u;
            *(float4*)&Vs[sw(a) >> 2]       = vv0;
            *(float4*)&Vs[sw(a + 16u) >> 2] = vv1;
        }
        // stage + transform P: warp wrp stages rows {wrp + r8*8}, lane = col
        #pragma unroll
        for (int hb = 0; hb < 4; hb++) {
            float v[8];
            #pragma unroll
            for (int r = 0; r < 8; r++) {
                int row = wrp + (hb * 8 + r) * 8;
                v[r] = __ldg(pbase + (size_t)row * SLEN + c * 32);
            }
            #pragma unroll
            for (int r = 0; r < 8; r++) {
                int row = wrp + (hb * 8 + r) * 8;
                float x = v[r];
                unsigned bits = __float_as_uint(fabsf(x));
                unsigned b = bits >> 18;
                float frac = (float)(bits & 0x3FFFFu) * (1.0f / 262144.0f);
                float t0 = ttab_s[b], t1 = ttab_s[b + 1];
                float t = fmaf(frac, t1 - t0, t0);
                t = (x > 0.0f) ? t : ((x < 0.0f) ? -t : 0.0f);
                Ts[row * 33 + lane] = t;
            }
        }
        // prefetch V chunk c+1 (uniform branch)
        if (c < 3) {
            const float* vp = vrow_ptr + (size_t)(c + 1) * 32 * HD;
            vv0 = *(const float4*)vp;
            vv1 = *(const float4*)(vp + 4);
        }
        __syncthreads();
        // math: rows ty*8..+8, cols tx*8..+8 (no row-sum work in this loop)
        #pragma unroll 4
        for (int k = 0; k < 32; k++) {
            unsigned a0 = (unsigned)k * 256u + (unsigned)tx * 32u;
            float4 b0 = *(const float4*)&Vs[sw(a0) >> 2];
            float4 b1 = *(const float4*)&Vs[sw(a0 + 16u) >> 2];
            ull bv0 = pack2(b0.x, b0.y), bv1 = pack2(b0.z, b0.w);
            ull bv2 = pack2(b1.x, b1.y), bv3 = pack2(b1.z, b1.w);
            #pragma unroll
            for (int ii = 0; ii < 8; ii++) {
                float av = Ts[(ty * 8 + ii) * 33 + k];  // 4 banks, 8-way bcast
                ull a2 = pack2(av, av);
                acc[ii][0] = fma2(a2, bv0, acc[ii][0]);
                acc[ii][1] = fma2(a2, bv1, acc[ii][1]);
                acc[ii][2] = fma2(a2, bv2, acc[ii][2]);
                acc[ii][3] = fma2(a2, bv3, acc[ii][3]);
            }
        }
        // row |sum| post-pass, k-sliced per tx (banks 8ty+tx: conflict-free)
        #pragma unroll
        for (int j = 0; j < 4; j++) {
            int k = j * 8 + tx;
            #pragma unroll
            for (int ii = 0; ii < 8; ii++)
                srow8[ii] += fabsf(Ts[(ty * 8 + ii) * 33 + k]);
        }
    }

    // reduce row sums across the 8 tx threads (lanes tx^1, tx^2, tx^4)
    #pragma unroll
    for (int ii = 0; ii < 8; ii++) {
        float s = srow8[ii];
        s += __shfl_xor_sync(0xffffffffu, s, 1);
        s += __shfl_xor_sync(0xffffffffu, s, 2);
        s += __shfl_xor_sync(0xffffffffu, s, 4);
        srow8[ii] = s;
    }
    if (tx == 0) {
        #pragma unroll
        for (int ii = 0; ii < 8; ii++)
            g_psum[ks * NROWS + i0 + ty * 8 + ii] = srow8[ii];
    }

    // partial outputs
    float* pout = g_pout + (size_t)ks * NROWS * HD;
    int d0 = tx * 8;
    #pragma unroll
    for (int ii = 0; ii < 8; ii++) {
        int lrow = ty * 8 + ii;
        float2 c0 = unpack2(acc[ii][0]);
        float2 c1 = unpack2(acc[ii][1]);
        float2 c2 = unpack2(acc[ii][2]);
        float2 c3 = unpack2(acc[ii][3]);
        size_t oidx = (size_t)(i0 + lrow) * HD + d0;
        *(float4*)&pout[oidx]     = make_float4(c0.x, c0.y, c1.x, c1.y);
        *(float4*)&pout[oidx + 4] = make_float4(c2.x, c2.y, c3.x, c3.y);
    }
}

// ---------------- kernel 4: combine partials ---------------------------------
__global__ __launch_bounds__(256) void fixup_kernel(float* __restrict__ O) {
    int idx = blockIdx.x * 256 + threadIdx.x;   // 0 .. 2M-1
    int row = idx >> 6;
    float s = 0.0f, o = 0.0f;
    #pragma unroll
    for (int p = 0; p < KSPLIT; p++) {
        s += g_psum[p * NROWS + row];
        o += g_pout[(size_t)p * NROWS * HD + idx];
    }
    O[idx] = o * (1.0f / s);
}

// ---------------- launcher ---------------------------------------------------
#define SMEM_OUT ((256 * 33 + 32 * 64 + NBINS + 1) * 4)

extern "C" void kernel_launch(void* const* d_in, const int* in_sizes, int n_in,
                              void* d_out, int out_size) {
    const float* Q = (const float*)d_in[0];
    const float* K = (const float*)d_in[1];
    const float* V = (const float*)d_in[2];
    float* O = (float*)d_out;

    static int attr_done = 0;
    if (!attr_done) {
        cudaFuncSetAttribute(out_kernel,
                             cudaFuncAttributeMaxDynamicSharedMemorySize, SMEM_OUT);
        attr_done = 1;
    }

    norms_kernel<<<8192, 256>>>(Q, K);
    score_kernel<<<dim3(8, 8, NBH), 256>>>(Q, K);
    scan_ttab_kernel<<<1, 1024>>>();
    out_kernel<<<1024, 256, SMEM_OUT>>>(V);
    fixup_kernel<<<NROWS * HD / 256, 256>>>(O);
}